// round 9
// baseline (speedup 1.0000x reference)
#include <cuda_runtime.h>
#include <math.h>

#define B     4096
#define NN    2048
#define NIN   512
#define NEV   1536
#define NOUT  256
#define TT    128
#define NSTG  12
#define BM    32
#define BK    32

// Column-major activations: g_act[node * B + batch]. 32 MB static scratch.
__device__ float g_act[NN * (size_t)B];

// shared memory layout (bytes)
#define OFF_WD   0                         // float [128][129]       diag W block
#define OFF_WS   66048                     // float2[32][64] swizzled node-pair W tile
#define OFF_AS   (66048 + 16384)           // float2[32][33]         duplicated (a,a) tile
#define OFF_ZS   (OFF_AS + 8448)           // float [128][33]        z / o staging
#define SMEM_TOTAL (OFF_ZS + 128*33*4)     // 107776 bytes

typedef unsigned long long u64;

__device__ __forceinline__ void fma2(u64 &c, u64 a, u64 w) {
    // packed 2-wide fp32 FMA (full-rate on sm_103a; plain FFMA reg-form is half-rate)
    asm("fma.rn.f32x2 %0, %1, %2, %0;" : "+l"(c) : "l"(a), "l"(w));
}

__global__ void __launch_bounds__(256, 1)
net_kernel(const float* __restrict__ W, const float* __restrict__ bias) {
    extern __shared__ char smem[];
    float*  Wd  = (float*) (smem + OFF_WD);
    float*  Wsf = (float*) (smem + OFF_WS);   // word-addressed swizzled pair store
    float2* As2 = (float2*)(smem + OFF_AS);   // (a,a) duplicated per batch
    float*  Zs  = (float*) (smem + OFF_ZS);

    const int tid   = threadIdx.x;
    const int bbase = blockIdx.x * BM;
    const int tx    = tid & 31;   // node-pair index within tile
    const int ty    = tid >> 5;   // batch group (0..7) -> 4 rows each

    for (int st = 0; st < NSTG; ++st) {
        const int node0 = st * TT;          // eval-row base in W (0-based)
        const int K     = NIN + node0;      // history length for this stage
        const int nch   = K >> 5;           // K / 32 chunks

        // ---- load the 128x128 strictly-lower diagonal W block (recurrence) ----
        for (int idx = tid; idx < TT * TT; idx += 256) {
            int t = idx >> 7, s = idx & 127;
            Wd[t * 129 + s] = W[(size_t)(node0 + t) * NN + (NIN + node0 + s)];
        }

        // ---- GEMM: Z[32 batch][128 nodes] = Act[:,0:K] @ Wblk^T ----
        // acc[i][j]: node pair (2*tx + 64*i, 2*tx+1 + 64*i), batch 4*ty + j
        u64 acc[2][4];
        #pragma unroll
        for (int i = 0; i < 2; i++)
            #pragma unroll
            for (int j = 0; j < 4; j++) acc[i][j] = 0ull;

        float pa[4]; float pw[16];
        {   // prefetch chunk 0 into registers (coalesced)
            const int b = tid & 31, kk = tid >> 5;
            #pragma unroll
            for (int ii = 0; ii < 4; ++ii)
                pa[ii] = g_act[(size_t)(kk + 8*ii) * B + bbase + b];
            const int k = tid & 31, tb = tid >> 5;
            #pragma unroll
            for (int jj = 0; jj < 16; ++jj)
                pw[jj] = W[(size_t)(node0 + tb + 8*jj) * NN + k];
        }

        for (int ch = 0; ch < nch; ++ch) {
            __syncthreads();
            {   // registers -> shared
                const int b = tid & 31, kk = tid >> 5;
                #pragma unroll
                for (int ii = 0; ii < 4; ++ii)
                    As2[(kk + 8*ii) * 33 + b] = make_float2(pa[ii], pa[ii]);
                const int k = tid & 31, tb = tid >> 5;
                #pragma unroll
                for (int jj = 0; jj < 16; ++jj) {
                    int n = tb + 8*jj;      // node 0..127
                    // swizzled node-pair layout: float2 idx = k*64 + ((n>>1) ^ (k&15))
                    Wsf[(k * 64 + ((n >> 1) ^ (k & 15))) * 2 + (n & 1)] = pw[jj];
                }
            }
            __syncthreads();
            if (ch + 1 < nch) {   // prefetch next chunk (LDGs overlap compute below)
                const int j0 = (ch + 1) << 5;
                const int b = tid & 31, kk = tid >> 5;
                #pragma unroll
                for (int ii = 0; ii < 4; ++ii)
                    pa[ii] = g_act[(size_t)(j0 + kk + 8*ii) * B + bbase + b];
                const int k = tid & 31, tb = tid >> 5;
                #pragma unroll
                for (int jj = 0; jj < 16; ++jj)
                    pw[jj] = W[(size_t)(node0 + tb + 8*jj) * NN + j0 + k];
            }
            #pragma unroll
            for (int kk2 = 0; kk2 < BK; ++kk2) {
                const int sw = (tx ^ (kk2 & 15));
                u64 w0 = *(const u64*)&Wsf[kk2 * 128 + 2*sw];        // nodes 2tx, 2tx+1
                u64 w1 = *(const u64*)&Wsf[kk2 * 128 + 2*sw + 64];   // nodes 2tx+64, 2tx+65
                #pragma unroll
                for (int j = 0; j < 4; ++j) {
                    u64 a = *(const u64*)&As2[kk2 * 33 + ty*4 + j];  // (a,a) broadcast
                    fma2(acc[0][j], a, w0);
                    fma2(acc[1][j], a, w1);
                }
            }
        }
        __syncthreads();

        // ---- stash z + bias into shared ----
        #pragma unroll
        for (int i = 0; i < 2; i++) {
            int t0 = 2*tx + 64*i;
            float b0 = __ldg(&bias[node0 + t0]);
            float b1 = __ldg(&bias[node0 + t0 + 1]);
            #pragma unroll
            for (int j = 0; j < 4; j++) {
                float2 v = *(float2*)&acc[i][j];
                int bl = ty*4 + j;
                Zs[ t0      * 33 + bl] = v.x + b0;
                Zs[(t0 + 1) * 33 + bl] = v.y + b1;
            }
        }
        __syncthreads();

        // ---- triangular recurrence: 128 sequential sigmoid steps ----
        // warp = 4 batch rows; lane l: row r = l>>3, slot-group g = l&7,
        // owns z for nodes t = 8*i + g, i = 0..15, all in registers.
        {
            const int r  = tx >> 3;
            const int g  = tx & 7;
            const int bl = ty * 4 + r;
            float z[16];
            #pragma unroll
            for (int i = 0; i < 16; i++) z[i] = Zs[(8*i + g) * 33 + bl];

            #pragma unroll
            for (int s = 0; s < 128; ++s) {
                float zv = __shfl_sync(0xffffffffu, z[s >> 3], (r << 3) | (s & 7));
                float t5 = fminf(fmaxf(5.0f * zv, -60.0f), 60.0f);
                float e  = __expf(-t5);                 // MUFU.EX2 path
                float o  = __fdividef(1.0f, 1.0f + e);  // MUFU.RCP path
                if ((s & 7) == g) z[s >> 3] = o;        // owner keeps output in place
                #pragma unroll
                for (int i = 0; i < 16; i++) {
                    int t = 8*i + g;
                    if (t > s) z[i] += Wd[t * 129 + s] * o;
                }
            }
            #pragma unroll
            for (int i = 0; i < 16; i++) Zs[(8*i + g) * 33 + bl] = z[i];  // now outputs o
        }
        __syncthreads();

        // ---- coalesced writeback of this stage's 128 output columns ----
        {
            const int b = tid & 31, t0 = tid >> 5;
            #pragma unroll
            for (int j = 0; j < 16; ++j) {
                int t = t0 + 8*j;
                g_act[(size_t)(NIN + node0 + t) * B + bbase + b] = Zs[t * 33 + b];
            }
        }
        // next-stage Wd writes are safe: all Wd reads finished before the
        // __syncthreads above; g_act writes become block-visible at the next
        // __syncthreads (chunk 0) before any chunk can read the new columns.
    }
}

// x [4096,512] row-major  ->  g_act[j*B + b]  (transpose via shared tile)
__global__ void init_kernel(const float* __restrict__ x) {
    __shared__ float tile[32][33];
    int j0 = blockIdx.x * 32;
    int b0 = blockIdx.y * 32;
    int tx = threadIdx.x & 31, ty = threadIdx.x >> 5;
    #pragma unroll
    for (int i = 0; i < 4; i++)
        tile[ty + 8*i][tx] = x[(size_t)(b0 + ty + 8*i) * NIN + j0 + tx];   // tile[b][j]
    __syncthreads();
    #pragma unroll
    for (int i = 0; i < 4; i++)
        g_act[(size_t)(j0 + ty + 8*i) * B + b0 + tx] = tile[tx][ty + 8*i];
}

// g_act last 256 columns -> d_out [4096,256] row-major
__global__ void out_kernel(float* __restrict__ out) {
    __shared__ float tile[32][33];
    int q0 = blockIdx.x * 32;
    int b0 = blockIdx.y * 32;
    int tx = threadIdx.x & 31, ty = threadIdx.x >> 5;
    #pragma unroll
    for (int i = 0; i < 4; i++)
        tile[ty + 8*i][tx] = g_act[(size_t)(NN - NOUT + q0 + ty + 8*i) * B + b0 + tx]; // tile[q][b]
    __syncthreads();
    #pragma unroll
    for (int i = 0; i < 4; i++)
        out[(size_t)(b0 + ty + 8*i) * NOUT + q0 + tx] = tile[tx][ty + 8*i];
}

extern "C" void kernel_launch(void* const* d_in, const int* in_sizes, int n_in,
                              void* d_out, int out_size) {
    const float* x = (const float*)d_in[0];   // [4096, 512]
    const float* W = (const float*)d_in[1];   // [1536, 2048]
    const float* b = (const float*)d_in[2];   // [1536]
    (void)in_sizes; (void)n_in; (void)out_size;

    cudaFuncSetAttribute(net_kernel, cudaFuncAttributeMaxDynamicSharedMemorySize, SMEM_TOTAL);

    init_kernel<<<dim3(NIN/32, B/32), 256>>>(x);
    net_kernel<<<B/BM, 256, SMEM_TOTAL>>>(W, b);
    out_kernel<<<dim3(NOUT/32, B/32), 256>>>((float*)d_out);
}

// round 11
// speedup vs baseline: 2.1038x; 2.1038x over previous
#include <cuda_runtime.h>
#include <cuda_bf16.h>
#include <math.h>
#include <stdint.h>

#define B      4096
#define NN     2048
#define NIN    512
#define NOUT   256
#define NSTG   12
#define NTILES 228               // sum over stages of (8+2*st)
#define CHBYTES 40960            // per-chunk buffer: A_hi 16K | A_lo 16K | B_hi 4K | B_lo 4K

// ---------------- static device scratch (no allocs) ----------------
__device__ __align__(16) unsigned char g_wtile[(size_t)NTILES * 32768]; // per chunk: A_hi 16K | A_lo 16K (SW128 images)
__device__ __align__(16) float         g_wdp[NSTG * 20480];             // diag W padded: [st][s*160 + g*20 + i]
__device__ __align__(16) unsigned char g_bact[(size_t)128 * 32 * 8192]; // per (cta,chunk): B_hi 4K | B_lo 4K (SW128 images)

// ---------------- smem layout (bytes) ----------------
#define OFF_WDP    122880        // after 3 x 40960 chunk buffers
#define OFF_ZS     204800        // 128*33*4 = 16896
#define SMEM_TOTAL 221696

__host__ __device__ __forceinline__ unsigned sw128(unsigned x) { return x ^ ((x >> 3) & 0x70); }

__device__ __forceinline__ uint32_t s2u(const void* p) { return (uint32_t)__cvta_generic_to_shared(p); }

__device__ __forceinline__ void cpa16(uint32_t dst, const void* src) {
    asm volatile("cp.async.cg.shared.global [%0], [%1], 16;" :: "r"(dst), "l"(src) : "memory");
}
#define CP_COMMIT()  asm volatile("cp.async.commit_group;" ::: "memory")
#define CP_WAIT2()   asm volatile("cp.async.wait_group 2;" ::: "memory")

__device__ __forceinline__ void ldsm4(uint32_t* r, uint32_t addr) {
    asm volatile("ldmatrix.sync.aligned.m8n8.x4.shared.b16 {%0,%1,%2,%3}, [%4];"
                 : "=r"(r[0]), "=r"(r[1]), "=r"(r[2]), "=r"(r[3]) : "r"(addr));
}
__device__ __forceinline__ void mma16816(float* d, const uint32_t* a, const uint32_t* b) {
    asm volatile("mma.sync.aligned.m16n8k16.row.col.f32.bf16.bf16.f32 "
                 "{%0,%1,%2,%3}, {%4,%5,%6,%7}, {%8,%9}, {%0,%1,%2,%3};"
                 : "+f"(d[0]), "+f"(d[1]), "+f"(d[2]), "+f"(d[3])
                 : "r"(a[0]), "r"(a[1]), "r"(a[2]), "r"(a[3]), "r"(b[0]), "r"(b[1]));
}
__device__ __forceinline__ uint32_t packhl(float v0, float v1, uint32_t& lp) {
    __nv_bfloat16 h0 = __float2bfloat16(v0), h1 = __float2bfloat16(v1);
    __nv_bfloat16 l0 = __float2bfloat16(v0 - __bfloat162float(h0));
    __nv_bfloat16 l1 = __float2bfloat16(v1 - __bfloat162float(h1));
    lp = ((uint32_t)__bfloat16_as_ushort(l1) << 16) | (uint32_t)__bfloat16_as_ushort(l0);
    return ((uint32_t)__bfloat16_as_ushort(h1) << 16) | (uint32_t)__bfloat16_as_ushort(h0);
}
__device__ __forceinline__ int stage_of(int g) {
    int s = 0;
    while (s + 1 < NSTG && (s + 1) * (s + 8) <= g) ++s;   // tb(s) = s*(s+7)
    return s;
}

// ---------------- prep kernels (deterministic, rerun every launch) ----------------
__global__ void prep_w(const float* __restrict__ W) {
    int tl = blockIdx.x;
    int st = stage_of(tl);
    int c = tl - st * (st + 7);
    unsigned char* dst = g_wtile + (size_t)tl * 32768;
    for (int e = threadIdx.x; e < 4096; e += 256) {
        int t = e >> 5, p = e & 31;
        const float* src = &W[(size_t)(st * 128 + t) * NN + c * 64 + 2 * p];
        uint32_t lp, hp = packhl(src[0], src[1], lp);
        unsigned off = sw128((unsigned)(t * 128 + 4 * p));
        *(uint32_t*)(dst + off)         = hp;
        *(uint32_t*)(dst + 16384 + off) = lp;
    }
}

__global__ void prep_wd(const float* __restrict__ W) {
    int e = blockIdx.x * 256 + threadIdx.x;            // 12*20480 entries
    if (e >= NSTG * 20480) return;
    int st = e / 20480, rem = e % 20480;
    int s = rem / 160, r2 = rem % 160;
    int g = r2 / 20, i = r2 % 20;
    float v = 0.f;
    if (i < 16) v = W[(size_t)(st * 128 + 8 * i + g) * NN + NIN + st * 128 + s];
    g_wdp[e] = v;   // zero above/on diagonal comes from the input mask itself
}

__global__ void init_kernel(const float* __restrict__ x) {
    int cta = blockIdx.x, ch = blockIdx.y;
    int p = threadIdx.x & 31, b0 = threadIdx.x >> 5;
    unsigned char* dst = g_bact + ((size_t)cta * 32 + ch) * 8192;
    #pragma unroll
    for (int j = 0; j < 4; ++j) {
        int b = b0 + 8 * j;
        const float* src = &x[(size_t)(cta * 32 + b) * NIN + ch * 64 + 2 * p];
        uint32_t lp, hp = packhl(src[0], src[1], lp);
        unsigned off = sw128((unsigned)(b * 128 + 4 * p));
        *(uint32_t*)(dst + off)        = hp;
        *(uint32_t*)(dst + 4096 + off) = lp;
    }
}

// ---------------- main kernel: 1 CTA = 32 batch rows, all 12 stages ----------------
__device__ __forceinline__ void issue_chunk(int g, int cta, uint32_t smem0, int tid) {
    int s = stage_of(g);
    int c = g - s * (s + 7);
    uint32_t dst = smem0 + (uint32_t)(g % 3) * CHBYTES;
    const unsigned char* srcA = g_wtile + (size_t)g * 32768;
    const unsigned char* srcB = g_bact + ((size_t)cta * 32 + c) * 8192;
    #pragma unroll
    for (int i = 0; i < 8; ++i) cpa16(dst + 16u * (tid + 256 * i), srcA + 16 * (tid + 256 * i));
    #pragma unroll
    for (int i = 0; i < 2; ++i) cpa16(dst + 32768u + 16u * (tid + 256 * i), srcB + 16 * (tid + 256 * i));
    if (c == 5) {   // diag W for stage s rides in this group (prev stage's WDP already consumed)
        const unsigned char* srcW = (const unsigned char*)(g_wdp + s * 20480);
        #pragma unroll
        for (int i = 0; i < 20; ++i) cpa16(smem0 + OFF_WDP + 16u * (tid + 256 * i), srcW + 16 * (tid + 256 * i));
    }
}

__global__ void __launch_bounds__(256, 1)
net_kernel(const float* __restrict__ bias, float* __restrict__ out) {
    extern __shared__ char smem[];
    float* Zs   = (float*)(smem + OFF_ZS);
    float* WdpF = (float*)(smem + OFF_WDP);
    const int tid = threadIdx.x, wid = tid >> 5, lid = tid & 31;
    const int cta = blockIdx.x, bbase = cta * 32;
    const uint32_t smem0 = s2u(smem);
    const int nb = wid * 16;                 // node base of this warp's M-strip

    // prologue: chunks 0,1,2 (all x-data for stage 0)
    for (int g = 0; g < 3; ++g) { issue_chunk(g, cta, smem0, tid); CP_COMMIT(); }

    int gidx = 0;
    for (int st = 0; st < NSTG; ++st) {
        const int nch = 8 + 2 * st;

        float d[4][4];
        #pragma unroll
        for (int nt = 0; nt < 4; ++nt)
            #pragma unroll
            for (int q = 0; q < 4; ++q) d[nt][q] = 0.f;

        for (int ch = 0; ch < nch; ++ch, ++gidx) {
            CP_WAIT2();                       // chunk gidx complete (this thread)
            __syncthreads();                  // ... for all threads

            const uint32_t buf = smem0 + (uint32_t)(gidx % 3) * CHBYTES;
            #pragma unroll
            for (int ks = 0; ks < 4; ++ks) {
                uint32_t ah[4], al[4], bh[8], bl[8];
                unsigned aoff = (unsigned)(nb + (lid & 15)) * 128 + ((lid >> 4) * 16 + ks * 32);
                ldsm4(ah, buf + sw128(aoff));
                ldsm4(al, buf + 16384 + sw128(aoff));
                unsigned nrow = (lid & 7) + ((lid >> 4) & 1) * 8;
                unsigned kb   = ((lid >> 3) & 1) * 16 + ks * 32;
                ldsm4(bh,     buf + 32768 + sw128(nrow * 128 + kb));
                ldsm4(bh + 4, buf + 32768 + sw128((nrow + 16) * 128 + kb));
                ldsm4(bl,     buf + 36864 + sw128(nrow * 128 + kb));
                ldsm4(bl + 4, buf + 36864 + sw128((nrow + 16) * 128 + kb));
                #pragma unroll
                for (int nt = 0; nt < 4; ++nt) {
                    mma16816(d[nt], ah, &bh[2 * nt]);   // Ah*Bh
                    mma16816(d[nt], ah, &bl[2 * nt]);   // Ah*Bl
                    mma16816(d[nt], al, &bh[2 * nt]);   // Al*Bh
                }
            }
            __syncthreads();                  // done reading buf before it is re-filled

            if (gidx + 3 < NTILES) issue_chunk(gidx + 3, cta, smem0, tid);
            CP_COMMIT();                      // one group per iteration (possibly empty)
        }

        // ---- epilogue: d-frags + bias -> Zs[node*33 + batch] ----
        {
            int m0 = nb + (lid >> 2), m1 = m0 + 8;
            float bi0 = __ldg(&bias[st * 128 + m0]);
            float bi1 = __ldg(&bias[st * 128 + m1]);
            #pragma unroll
            for (int nt = 0; nt < 4; ++nt) {
                int c = nt * 8 + 2 * (lid & 3);
                Zs[m0 * 33 + c]     = d[nt][0] + bi0;
                Zs[m0 * 33 + c + 1] = d[nt][1] + bi0;
                Zs[m1 * 33 + c]     = d[nt][2] + bi1;
                Zs[m1 * 33 + c + 1] = d[nt][3] + bi1;
            }
        }
        __syncthreads();

        // ---- triangular recurrence: 128 sequential sigmoid steps (guard-free) ----
        {
            const int r = lid >> 3, g = lid & 7;
            const int bl2 = wid * 4 + r;
            float z[16];
            #pragma unroll
            for (int i = 0; i < 16; i++) z[i] = Zs[(8 * i + g) * 33 + bl2];

            #pragma unroll
            for (int s = 0; s < 128; ++s) {
                float zv = __shfl_sync(0xffffffffu, z[s >> 3], (r << 3) | (s & 7));
                float t5 = fminf(fmaxf(5.0f * zv, -60.0f), 60.0f);
                float o  = __fdividef(1.0f, 1.0f + __expf(-t5));
                if ((s & 7) == g) z[s >> 3] = o;
                const float4* w4 = (const float4*)&WdpF[s * 160 + g * 20];
                float4 w0 = w4[0], w1 = w4[1], w2 = w4[2], w3 = w4[3];
                z[0] += w0.x*o; z[1] += w0.y*o; z[2]  += w0.z*o; z[3]  += w0.w*o;
                z[4] += w1.x*o; z[5] += w1.y*o; z[6]  += w1.z*o; z[7]  += w1.w*o;
                z[8] += w2.x*o; z[9] += w2.y*o; z[10] += w2.z*o; z[11] += w2.w*o;
                z[12]+= w3.x*o; z[13]+= w3.y*o; z[14] += w3.z*o; z[15] += w3.w*o;
            }
            #pragma unroll
            for (int i = 0; i < 16; i++) Zs[(8 * i + g) * 33 + bl2] = z[i];   // now the o's
        }
        __syncthreads();

        // ---- writeback: new activations as bf16 hi/lo B-tile images (+ f32 out for st>=10) ----
        {
            unsigned char* dst0 = g_bact + ((size_t)cta * 32 + 8 + 2 * st) * 8192;
            #pragma unroll
            for (int c = 0; c < 2; ++c) {
                unsigned char* dst = dst0 + c * 8192;
                #pragma unroll
                for (int jj = 0; jj < 4; ++jj) {
                    int b  = wid + 8 * jj;
                    int tl = c * 64 + 2 * lid;
                    float v0 = Zs[tl * 33 + b], v1 = Zs[(tl + 1) * 33 + b];
                    uint32_t lp, hp = packhl(v0, v1, lp);
                    unsigned off = sw128((unsigned)(b * 128 + 4 * lid));
                    *(uint32_t*)(dst + off)        = hp;
                    *(uint32_t*)(dst + 4096 + off) = lp;
                    if (st >= 10) {
                        int q = 128 * (st - 10) + tl;
                        *(float2*)&out[(size_t)(bbase + b) * NOUT + q] = make_float2(v0, v1);
                    }
                }
            }
        }
        __syncthreads();   // writeback visible (CTA scope) before any cp.async reads it
    }
}

extern "C" void kernel_launch(void* const* d_in, const int* in_sizes, int n_in,
                              void* d_out, int out_size) {
    const float* x = (const float*)d_in[0];   // [4096, 512]
    const float* W = (const float*)d_in[1];   // [1536, 2048]
    const float* b = (const float*)d_in[2];   // [1536]
    (void)in_sizes; (void)n_in; (void)out_size;

    cudaFuncSetAttribute(net_kernel, cudaFuncAttributeMaxDynamicSharedMemorySize, SMEM_TOTAL);

    prep_w<<<NTILES, 256>>>(W);
    prep_wd<<<(NSTG * 20480 + 255) / 256, 256>>>(W);
    init_kernel<<<dim3(128, 8), 256>>>(x);
    net_kernel<<<128, 256, SMEM_TOTAL>>>(b, (float*)d_out);
}